// round 7
// baseline (speedup 1.0000x reference)
#include <cuda_runtime.h>

// ---------------------------------------------------------------------------
// ARAP forward — batch-interleaved gather layout (R6) + occupancy cap + B=4
// specialization.
// g_pack2 line = vertex j's 4 batches x {rest,def} float4 = one 128B line.
// Thread t -> vertex i = t>>2, batch b = t&3: each gather LDG.128 touches 8
// lines per warp. Reg cap (256,5) -> 40 warps/SM; spills land in the SVD
// tail where L1 has headroom.
// ---------------------------------------------------------------------------

#define MAXV (4 * 65536)

__device__ float4 g_pack2[2 * MAXV];   // index 2*(j*4+b) rest, +1 deformed

// B==4 pack: 128 vertices x 4 batches per 512-thread block, smem-staged.
__global__ void __launch_bounds__(512)
pack4_smem(const float* __restrict__ x1, const float* __restrict__ x2, int N) {
    __shared__ float s1[4 * 385];   // 384 floats per batch chunk, +1 pad
    __shared__ float s2[4 * 385];
    int j0  = blockIdx.x * 128;
    int tid = threadIdx.x;

    for (int idx = tid; idx < 1536; idx += 512) {
        int b = idx / 384, k = idx - b * 384;
        s1[b * 385 + k] = x1[((size_t)b * N + j0) * 3 + k];
        s2[b * 385 + k] = x2[((size_t)b * N + j0) * 3 + k];
    }
    __syncthreads();

    int v = tid >> 2, b = tid & 3;
    int j = j0 + v;
    int si = b * 385 + v * 3;
    int t = j * 4 + b;
    g_pack2[2 * t]     = make_float4(s1[si], s1[si + 1], s1[si + 2], 0.f);
    g_pack2[2 * t + 1] = make_float4(s2[si], s2[si + 1], s2[si + 2], 0.f);
}

// Generic fallback pack (any B).
__global__ void pack_naive(const float* __restrict__ x1,
                           const float* __restrict__ x2,
                           int B, int N) {
    int t = blockIdx.x * blockDim.x + threadIdx.x;
    if (t >= B * N) return;
    int i = t / B, b = t - i * B;
    const float* p1 = x1 + ((size_t)b * N + i) * 3;
    const float* p2 = x2 + ((size_t)b * N + i) * 3;
    g_pack2[2 * t]     = make_float4(p1[0], p1[1], p1[2], 0.f);
    g_pack2[2 * t + 1] = make_float4(p2[0], p2[1], p2[2], 0.f);
}

__device__ __forceinline__ void jrot(float A[3][3], float V[3][3], int p, int q) {
    float apq = A[p][q];
    if (fabsf(apq) > 1e-30f) {
        float app = A[p][p], aqq = A[q][q];
        float tau = (aqq - app) / (2.0f * apq);
        float tt  = copysignf(1.0f, tau) / (fabsf(tau) + sqrtf(1.0f + tau * tau));
        float c   = 1.0f / sqrtf(1.0f + tt * tt);
        float s   = tt * c;
        int r = 3 - p - q;
        float arp = A[r][p], arq = A[r][q];
        A[p][p] = app - tt * apq;
        A[q][q] = aqq + tt * apq;
        A[p][q] = 0.f; A[q][p] = 0.f;
        float nrp = c * arp - s * arq;
        float nrq = s * arp + c * arq;
        A[r][p] = nrp; A[p][r] = nrp;
        A[r][q] = nrq; A[q][r] = nrq;
        #pragma unroll
        for (int i = 0; i < 3; i++) {
            float vip = V[i][p], viq = V[i][q];
            V[i][p] = c * vip - s * viq;
            V[i][q] = s * vip + c * viq;
        }
    }
}

__device__ __forceinline__ void swap_col(float V[3][3], int a, int b) {
    #pragma unroll
    for (int i = 0; i < 3; i++) {
        float tmp = V[i][a]; V[i][a] = V[i][b]; V[i][b] = tmp;
    }
}

// Shared body: computes SVD/rotation/energies from accumulated moments and
// writes outputs for cell (b,i).
__device__ __forceinline__ void solve_and_store(
    float S00, float S01, float S02, float S10, float S11, float S12,
    float S20, float S21, float S22,
    float p00, float p01, float p02, float p11, float p12, float p22,
    float q0, float q1, float q2,
    const float* __restrict__ arapW, float* __restrict__ out,
    int b, int i, int N, int total)
{
    float S[3][3] = {{S00,S01,S02},{S10,S11,S12},{S20,S21,S22}};
    float A[3][3];
    #pragma unroll
    for (int p = 0; p < 3; p++)
        #pragma unroll
        for (int q = 0; q < 3; q++)
            A[p][q] = S[0][p] * S[0][q] + S[1][p] * S[1][q] + S[2][p] * S[2][q];

    float V[3][3] = {{1.f,0.f,0.f},{0.f,1.f,0.f},{0.f,0.f,1.f}};
    #pragma unroll
    for (int sw = 0; sw < 6; sw++) {
        jrot(A, V, 0, 1);
        jrot(A, V, 0, 2);
        jrot(A, V, 1, 2);
    }

    if (A[0][0] < A[1][1]) { float tmp=A[0][0]; A[0][0]=A[1][1]; A[1][1]=tmp; swap_col(V,0,1); }
    if (A[0][0] < A[2][2]) { float tmp=A[0][0]; A[0][0]=A[2][2]; A[2][2]=tmp; swap_col(V,0,2); }
    if (A[1][1] < A[2][2]) { float tmp=A[1][1]; A[1][1]=A[2][2]; A[2][2]=tmp; swap_col(V,1,2); }

    float v0x=V[0][0], v0y=V[1][0], v0z=V[2][0];
    float v1x=V[0][1], v1y=V[1][1], v1z=V[2][1];
    float v2x=V[0][2], v2y=V[1][2], v2z=V[2][2];

    float u0x = S[0][0]*v0x + S[0][1]*v0y + S[0][2]*v0z;
    float u0y = S[1][0]*v0x + S[1][1]*v0y + S[1][2]*v0z;
    float u0z = S[2][0]*v0x + S[2][1]*v0y + S[2][2]*v0z;
    float u1x = S[0][0]*v1x + S[0][1]*v1y + S[0][2]*v1z;
    float u1y = S[1][0]*v1x + S[1][1]*v1y + S[1][2]*v1z;
    float u1z = S[2][0]*v1x + S[2][1]*v1y + S[2][2]*v1z;
    float u2x = S[0][0]*v2x + S[0][1]*v2y + S[0][2]*v2z;
    float u2y = S[1][0]*v2x + S[1][1]*v2y + S[1][2]*v2z;
    float u2z = S[2][0]*v2x + S[2][1]*v2y + S[2][2]*v2z;

    float n0 = rsqrtf(fmaxf(u0x*u0x + u0y*u0y + u0z*u0z, 1e-30f));
    float n1 = rsqrtf(fmaxf(u1x*u1x + u1y*u1y + u1z*u1z, 1e-30f));
    float n2 = rsqrtf(fmaxf(u2x*u2x + u2y*u2y + u2z*u2z, 1e-30f));
    u0x*=n0; u0y*=n0; u0z*=n0;
    u1x*=n1; u1y*=n1; u1z*=n1;
    u2x*=n2; u2y*=n2; u2z*=n2;

    float detS = S[0][0]*(S[1][1]*S[2][2] - S[1][2]*S[2][1])
               - S[0][1]*(S[1][0]*S[2][2] - S[1][2]*S[2][0])
               + S[0][2]*(S[1][0]*S[2][1] - S[1][1]*S[2][0]);
    float sgn = (detS < 0.f) ? -1.f : 1.f;
    u2x *= sgn; u2y *= sgn; u2z *= sgn;

    float R00 = v0x*u0x + v1x*u1x + v2x*u2x;
    float R01 = v0x*u0y + v1x*u1y + v2x*u2y;
    float R02 = v0x*u0z + v1x*u1z + v2x*u2z;
    float R10 = v0y*u0x + v1y*u1x + v2y*u2x;
    float R11 = v0y*u0y + v1y*u1y + v2y*u2y;
    float R12 = v0y*u0z + v1y*u1z + v2y*u2z;
    float R20 = v0z*u0x + v1z*u1x + v2z*u2x;
    float R21 = v0z*u0y + v1z*u1y + v2z*u2y;
    float R22 = v0z*u0z + v1z*u1z + v2z*u2z;

    float e0 = q0
        - 2.f * (R00*S[0][0] + R01*S[1][0] + R02*S[2][0])
        + R00*R00*p00 + R01*R01*p11 + R02*R02*p22
        + 2.f * (R00*R01*p01 + R00*R02*p02 + R01*R02*p12);
    float e1 = q1
        - 2.f * (R10*S[0][1] + R11*S[1][1] + R12*S[2][1])
        + R10*R10*p00 + R11*R11*p11 + R12*R12*p22
        + 2.f * (R10*R11*p01 + R10*R12*p02 + R11*R12*p12);
    float e2 = q2
        - 2.f * (R20*S[0][2] + R21*S[1][2] + R22*S[2][2])
        + R20*R20*p00 + R21*R21*p11 + R22*R22*p22
        + 2.f * (R20*R21*p01 + R20*R22*p02 + R21*R22*p12);
    e0 = fmaxf(e0, 0.f); e1 = fmaxf(e1, 0.f); e2 = fmaxf(e2, 0.f);

    float aw = arapW[0];
    int told = b * N + i;
    size_t eo = (size_t)told * 3;
    out[eo + 0] = aw * e0;
    out[eo + 1] = aw * e1;
    out[eo + 2] = aw * e2;

    size_t ro = (size_t)total * 3 + (size_t)told * 9;
    out[ro + 0] = R00; out[ro + 1] = R01; out[ro + 2] = R02;
    out[ro + 3] = R10; out[ro + 4] = R11; out[ro + 5] = R12;
    out[ro + 6] = R20; out[ro + 7] = R21; out[ro + 8] = R22;
}

#define EDGE_ACC(Bv, j_, w_)                                                 \
    {                                                                        \
        const float4* pp = &g_pack2[2 * ((j_) * (Bv) + b)];                  \
        float4 p1v = pp[0], p2v = pp[1];                                     \
        float d1x = c1.x - p1v.x, d1y = c1.y - p1v.y, d1z = c1.z - p1v.z;    \
        float d2x = c2.x - p2v.x, d2y = c2.y - p2v.y, d2z = c2.z - p2v.z;    \
        float wx = (w_) * d1x, wy = (w_) * d1y, wz = (w_) * d1z;             \
        S00 += wx * d2x; S01 += wx * d2y; S02 += wx * d2z;                   \
        S10 += wy * d2x; S11 += wy * d2y; S12 += wy * d2z;                   \
        S20 += wz * d2x; S21 += wz * d2y; S22 += wz * d2z;                   \
        p00 += wx * d1x; p01 += wx * d1y; p02 += wx * d1z;                   \
        p11 += wy * d1y; p12 += wy * d1z; p22 += wz * d1z;                   \
        float vx = (w_) * d2x, vy = (w_) * d2y, vz = (w_) * d2z;             \
        q0 += vx * d2x; q1 += vy * d2y; q2 += vz * d2z;                      \
    }

// Specialized B==4, K==16 main kernel; reg-capped for 5 blocks/SM.
__global__ void __launch_bounds__(256, 5)
arap_main4(const int*   __restrict__ nbrList,
           const float* __restrict__ wMat,
           const float* __restrict__ arapW,
           float*       __restrict__ out,
           int N)
{
    int t = blockIdx.x * blockDim.x + threadIdx.x;
    int total = 4 * N;
    if (t >= total) return;
    int i = t >> 2;
    int b = t & 3;

    float4 c1 = g_pack2[2 * t];
    float4 c2 = g_pack2[2 * t + 1];
    int start = i << 4;     // accN[i] = 16*i, verified by host-side guard

    float S00=0.f,S01=0.f,S02=0.f,S10=0.f,S11=0.f,S12=0.f,S20=0.f,S21=0.f,S22=0.f;
    float p00=0.f,p01=0.f,p02=0.f,p11=0.f,p12=0.f,p22=0.f;
    float q0=0.f,q1=0.f,q2=0.f;

    const int4*   nb4 = (const int4*)(nbrList + start);
    const float4* wv4 = (const float4*)(wMat + start);
    #pragma unroll
    for (int g = 0; g < 4; g++) {
        int4   nb = nb4[g];
        float4 wv = wv4[g];
        EDGE_ACC(4, nb.x, wv.x)
        EDGE_ACC(4, nb.y, wv.y)
        EDGE_ACC(4, nb.z, wv.z)
        EDGE_ACC(4, nb.w, wv.w)
    }

    solve_and_store(S00,S01,S02,S10,S11,S12,S20,S21,S22,
                    p00,p01,p02,p11,p12,p22,q0,q1,q2,
                    arapW, out, b, i, N, total);
}

// Generic fallback (any B / ragged CSR).
__global__ void __launch_bounds__(256)
arap_main_gen(const int*   __restrict__ nbrList,
              const int*   __restrict__ numN,
              const int*   __restrict__ accN,
              const float* __restrict__ wMat,
              const float* __restrict__ arapW,
              float*       __restrict__ out,
              int B, int N)
{
    int t = blockIdx.x * blockDim.x + threadIdx.x;
    int total = B * N;
    if (t >= total) return;
    int i = t / B;
    int b = t - i * B;

    float4 c1 = g_pack2[2 * t];
    float4 c2 = g_pack2[2 * t + 1];
    int start = accN[i];
    int cnt   = numN[i];

    float S00=0.f,S01=0.f,S02=0.f,S10=0.f,S11=0.f,S12=0.f,S20=0.f,S21=0.f,S22=0.f;
    float p00=0.f,p01=0.f,p02=0.f,p11=0.f,p12=0.f,p22=0.f;
    float q0=0.f,q1=0.f,q2=0.f;

    for (int k = 0; k < cnt; k++) {
        int   j = nbrList[start + k];
        float w = wMat[start + k];
        EDGE_ACC(B, j, w)
    }

    solve_and_store(S00,S01,S02,S10,S11,S12,S20,S21,S22,
                    p00,p01,p02,p11,p12,p22,q0,q1,q2,
                    arapW, out, b, i, N, total);
}

extern "C" void kernel_launch(void* const* d_in, const int* in_sizes, int n_in,
                              void* d_out, int out_size) {
    const float* xyz1 = (const float*)d_in[0];
    const float* xyz2 = (const float*)d_in[1];
    const int*   nbr  = (const int*)d_in[2];
    const int*   numN = (const int*)d_in[3];
    const int*   accN = (const int*)d_in[4];
    const float* wM   = (const float*)d_in[5];
    const float* aw   = (const float*)d_in[6];

    int N = in_sizes[3];                 // numNeighbors has N entries
    int B = in_sizes[0] / (3 * N);       // xyz1 is B*N*3
    int E = in_sizes[2];                 // neighborList length
    int total = B * N;

    int threads = 256;
    int blocks = (total + threads - 1) / threads;

    bool fast = (B == 4) && ((N & 127) == 0) && (E == 16 * N);

    if (fast) {
        pack4_smem<<<N / 128, 512>>>(xyz1, xyz2, N);
        arap_main4<<<blocks, threads>>>(nbr, wM, aw, (float*)d_out, N);
    } else {
        pack_naive<<<blocks, threads>>>(xyz1, xyz2, B, N);
        arap_main_gen<<<blocks, threads>>>(nbr, numN, accN, wM, aw,
                                           (float*)d_out, B, N);
    }
}

// round 8
// speedup vs baseline: 1.2039x; 1.2039x over previous
#include <cuda_runtime.h>

// ---------------------------------------------------------------------------
// ARAP forward — batch-interleaved gather layout, B=4 specialized, fast SVD.
// g_pack2 line = vertex j's 4 batches x {rest,def} float4 = one 128B line.
// Thread t -> vertex i = t>>2, batch b = t&3: each gather LDG.128 touches 8
// lines per warp (4x fewer L1 wavefronts than naive).
// Jacobi: 4 sweeps, __fdividef + rsqrtf (kernel is ~55% issue-bound; the 18
// IEEE FDIVs were ~25% of the instruction stream).
// NO register cap: proven twice (R4, R7) that spill tax > occupancy gain.
// ---------------------------------------------------------------------------

#define MAXV (4 * 65536)

__device__ float4 g_pack2[2 * MAXV];   // index 2*(j*4+b) rest, +1 deformed

// B==4 pack: 128 vertices x 4 batches per 512-thread block, smem-staged.
__global__ void __launch_bounds__(512)
pack4_smem(const float* __restrict__ x1, const float* __restrict__ x2, int N) {
    __shared__ float s1[4 * 385];
    __shared__ float s2[4 * 385];
    int j0  = blockIdx.x * 128;
    int tid = threadIdx.x;

    for (int idx = tid; idx < 1536; idx += 512) {
        int b = idx / 384, k = idx - b * 384;
        s1[b * 385 + k] = x1[((size_t)b * N + j0) * 3 + k];
        s2[b * 385 + k] = x2[((size_t)b * N + j0) * 3 + k];
    }
    __syncthreads();

    int v = tid >> 2, b = tid & 3;
    int j = j0 + v;
    int si = b * 385 + v * 3;
    int t = j * 4 + b;
    g_pack2[2 * t]     = make_float4(s1[si], s1[si + 1], s1[si + 2], 0.f);
    g_pack2[2 * t + 1] = make_float4(s2[si], s2[si + 1], s2[si + 2], 0.f);
}

// Generic fallback pack (any B).
__global__ void pack_naive(const float* __restrict__ x1,
                           const float* __restrict__ x2,
                           int B, int N) {
    int t = blockIdx.x * blockDim.x + threadIdx.x;
    if (t >= B * N) return;
    int i = t / B, b = t - i * B;
    const float* p1 = x1 + ((size_t)b * N + i) * 3;
    const float* p2 = x2 + ((size_t)b * N + i) * 3;
    g_pack2[2 * t]     = make_float4(p1[0], p1[1], p1[2], 0.f);
    g_pack2[2 * t + 1] = make_float4(p2[0], p2[1], p2[2], 0.f);
}

// Fast Jacobi rotation: __fdividef for tau, rsqrtf for c.
__device__ __forceinline__ void jrot(float A[3][3], float V[3][3], int p, int q) {
    float apq = A[p][q];
    if (fabsf(apq) > 1e-30f) {
        float app = A[p][p], aqq = A[q][q];
        float tau = __fdividef(aqq - app, 2.0f * apq);
        float tt  = __fdividef(copysignf(1.0f, tau),
                               fabsf(tau) + sqrtf(1.0f + tau * tau));
        float c   = rsqrtf(1.0f + tt * tt);
        float s   = tt * c;
        int r = 3 - p - q;
        float arp = A[r][p], arq = A[r][q];
        A[p][p] = app - tt * apq;
        A[q][q] = aqq + tt * apq;
        A[p][q] = 0.f; A[q][p] = 0.f;
        float nrp = c * arp - s * arq;
        float nrq = s * arp + c * arq;
        A[r][p] = nrp; A[p][r] = nrp;
        A[r][q] = nrq; A[q][r] = nrq;
        #pragma unroll
        for (int i = 0; i < 3; i++) {
            float vip = V[i][p], viq = V[i][q];
            V[i][p] = c * vip - s * viq;
            V[i][q] = s * vip + c * viq;
        }
    }
}

__device__ __forceinline__ void swap_col(float V[3][3], int a, int b) {
    #pragma unroll
    for (int i = 0; i < 3; i++) {
        float tmp = V[i][a]; V[i][a] = V[i][b]; V[i][b] = tmp;
    }
}

__device__ __forceinline__ void solve_and_store(
    float S00, float S01, float S02, float S10, float S11, float S12,
    float S20, float S21, float S22,
    float p00, float p01, float p02, float p11, float p12, float p22,
    float q0, float q1, float q2,
    const float* __restrict__ arapW, float* __restrict__ out,
    int b, int i, int N, int total)
{
    float S[3][3] = {{S00,S01,S02},{S10,S11,S12},{S20,S21,S22}};
    float A[3][3];
    #pragma unroll
    for (int p = 0; p < 3; p++)
        #pragma unroll
        for (int q = 0; q < 3; q++)
            A[p][q] = S[0][p] * S[0][q] + S[1][p] * S[1][q] + S[2][p] * S[2][q];

    float V[3][3] = {{1.f,0.f,0.f},{0.f,1.f,0.f},{0.f,0.f,1.f}};
    #pragma unroll
    for (int sw = 0; sw < 4; sw++) {
        jrot(A, V, 0, 1);
        jrot(A, V, 0, 2);
        jrot(A, V, 1, 2);
    }

    if (A[0][0] < A[1][1]) { float tmp=A[0][0]; A[0][0]=A[1][1]; A[1][1]=tmp; swap_col(V,0,1); }
    if (A[0][0] < A[2][2]) { float tmp=A[0][0]; A[0][0]=A[2][2]; A[2][2]=tmp; swap_col(V,0,2); }
    if (A[1][1] < A[2][2]) { float tmp=A[1][1]; A[1][1]=A[2][2]; A[2][2]=tmp; swap_col(V,1,2); }

    float v0x=V[0][0], v0y=V[1][0], v0z=V[2][0];
    float v1x=V[0][1], v1y=V[1][1], v1z=V[2][1];
    float v2x=V[0][2], v2y=V[1][2], v2z=V[2][2];

    float u0x = S[0][0]*v0x + S[0][1]*v0y + S[0][2]*v0z;
    float u0y = S[1][0]*v0x + S[1][1]*v0y + S[1][2]*v0z;
    float u0z = S[2][0]*v0x + S[2][1]*v0y + S[2][2]*v0z;
    float u1x = S[0][0]*v1x + S[0][1]*v1y + S[0][2]*v1z;
    float u1y = S[1][0]*v1x + S[1][1]*v1y + S[1][2]*v1z;
    float u1z = S[2][0]*v1x + S[2][1]*v1y + S[2][2]*v1z;
    float u2x = S[0][0]*v2x + S[0][1]*v2y + S[0][2]*v2z;
    float u2y = S[1][0]*v2x + S[1][1]*v2y + S[1][2]*v2z;
    float u2z = S[2][0]*v2x + S[2][1]*v2y + S[2][2]*v2z;

    float n0 = rsqrtf(fmaxf(u0x*u0x + u0y*u0y + u0z*u0z, 1e-30f));
    float n1 = rsqrtf(fmaxf(u1x*u1x + u1y*u1y + u1z*u1z, 1e-30f));
    float n2 = rsqrtf(fmaxf(u2x*u2x + u2y*u2y + u2z*u2z, 1e-30f));
    u0x*=n0; u0y*=n0; u0z*=n0;
    u1x*=n1; u1y*=n1; u1z*=n1;
    u2x*=n2; u2y*=n2; u2z*=n2;

    float detS = S[0][0]*(S[1][1]*S[2][2] - S[1][2]*S[2][1])
               - S[0][1]*(S[1][0]*S[2][2] - S[1][2]*S[2][0])
               + S[0][2]*(S[1][0]*S[2][1] - S[1][1]*S[2][0]);
    float sgn = (detS < 0.f) ? -1.f : 1.f;
    u2x *= sgn; u2y *= sgn; u2z *= sgn;

    float R00 = v0x*u0x + v1x*u1x + v2x*u2x;
    float R01 = v0x*u0y + v1x*u1y + v2x*u2y;
    float R02 = v0x*u0z + v1x*u1z + v2x*u2z;
    float R10 = v0y*u0x + v1y*u1x + v2y*u2x;
    float R11 = v0y*u0y + v1y*u1y + v2y*u2y;
    float R12 = v0y*u0z + v1y*u1z + v2y*u2z;
    float R20 = v0z*u0x + v1z*u1x + v2z*u2x;
    float R21 = v0z*u0y + v1z*u1y + v2z*u2y;
    float R22 = v0z*u0z + v1z*u1z + v2z*u2z;

    float e0 = q0
        - 2.f * (R00*S[0][0] + R01*S[1][0] + R02*S[2][0])
        + R00*R00*p00 + R01*R01*p11 + R02*R02*p22
        + 2.f * (R00*R01*p01 + R00*R02*p02 + R01*R02*p12);
    float e1 = q1
        - 2.f * (R10*S[0][1] + R11*S[1][1] + R12*S[2][1])
        + R10*R10*p00 + R11*R11*p11 + R12*R12*p22
        + 2.f * (R10*R11*p01 + R10*R12*p02 + R11*R12*p12);
    float e2 = q2
        - 2.f * (R20*S[0][2] + R21*S[1][2] + R22*S[2][2])
        + R20*R20*p00 + R21*R21*p11 + R22*R22*p22
        + 2.f * (R20*R21*p01 + R20*R22*p02 + R21*R22*p12);
    e0 = fmaxf(e0, 0.f); e1 = fmaxf(e1, 0.f); e2 = fmaxf(e2, 0.f);

    float aw = arapW[0];
    int told = b * N + i;
    size_t eo = (size_t)told * 3;
    out[eo + 0] = aw * e0;
    out[eo + 1] = aw * e1;
    out[eo + 2] = aw * e2;

    size_t ro = (size_t)total * 3 + (size_t)told * 9;
    out[ro + 0] = R00; out[ro + 1] = R01; out[ro + 2] = R02;
    out[ro + 3] = R10; out[ro + 4] = R11; out[ro + 5] = R12;
    out[ro + 6] = R20; out[ro + 7] = R21; out[ro + 8] = R22;
}

#define EDGE_ACC(Bv, j_, w_)                                                 \
    {                                                                        \
        const float4* pp = &g_pack2[2 * ((j_) * (Bv) + b)];                  \
        float4 p1v = pp[0], p2v = pp[1];                                     \
        float d1x = c1.x - p1v.x, d1y = c1.y - p1v.y, d1z = c1.z - p1v.z;    \
        float d2x = c2.x - p2v.x, d2y = c2.y - p2v.y, d2z = c2.z - p2v.z;    \
        float wx = (w_) * d1x, wy = (w_) * d1y, wz = (w_) * d1z;             \
        S00 += wx * d2x; S01 += wx * d2y; S02 += wx * d2z;                   \
        S10 += wy * d2x; S11 += wy * d2y; S12 += wy * d2z;                   \
        S20 += wz * d2x; S21 += wz * d2y; S22 += wz * d2z;                   \
        p00 += wx * d1x; p01 += wx * d1y; p02 += wx * d1z;                   \
        p11 += wy * d1y; p12 += wy * d1z; p22 += wz * d1z;                   \
        float vx = (w_) * d2x, vy = (w_) * d2y, vz = (w_) * d2z;             \
        q0 += vx * d2x; q1 += vy * d2y; q2 += vz * d2z;                      \
    }

// Specialized B==4, K==16 main kernel. NO reg cap.
__global__ void __launch_bounds__(256)
arap_main4(const int*   __restrict__ nbrList,
           const float* __restrict__ wMat,
           const float* __restrict__ arapW,
           float*       __restrict__ out,
           int N)
{
    int t = blockIdx.x * blockDim.x + threadIdx.x;
    int total = 4 * N;
    if (t >= total) return;
    int i = t >> 2;
    int b = t & 3;

    float4 c1 = g_pack2[2 * t];
    float4 c2 = g_pack2[2 * t + 1];
    int start = i << 4;     // accN[i] = 16*i, guaranteed by host-side guard

    float S00=0.f,S01=0.f,S02=0.f,S10=0.f,S11=0.f,S12=0.f,S20=0.f,S21=0.f,S22=0.f;
    float p00=0.f,p01=0.f,p02=0.f,p11=0.f,p12=0.f,p22=0.f;
    float q0=0.f,q1=0.f,q2=0.f;

    const int4*   nb4 = (const int4*)(nbrList + start);
    const float4* wv4 = (const float4*)(wMat + start);
    #pragma unroll
    for (int g = 0; g < 4; g++) {
        int4   nb = nb4[g];
        float4 wv = wv4[g];
        EDGE_ACC(4, nb.x, wv.x)
        EDGE_ACC(4, nb.y, wv.y)
        EDGE_ACC(4, nb.z, wv.z)
        EDGE_ACC(4, nb.w, wv.w)
    }

    solve_and_store(S00,S01,S02,S10,S11,S12,S20,S21,S22,
                    p00,p01,p02,p11,p12,p22,q0,q1,q2,
                    arapW, out, b, i, N, total);
}

// Generic fallback (any B / ragged CSR).
__global__ void __launch_bounds__(256)
arap_main_gen(const int*   __restrict__ nbrList,
              const int*   __restrict__ numN,
              const int*   __restrict__ accN,
              const float* __restrict__ wMat,
              const float* __restrict__ arapW,
              float*       __restrict__ out,
              int B, int N)
{
    int t = blockIdx.x * blockDim.x + threadIdx.x;
    int total = B * N;
    if (t >= total) return;
    int i = t / B;
    int b = t - i * B;

    float4 c1 = g_pack2[2 * t];
    float4 c2 = g_pack2[2 * t + 1];
    int start = accN[i];
    int cnt   = numN[i];

    float S00=0.f,S01=0.f,S02=0.f,S10=0.f,S11=0.f,S12=0.f,S20=0.f,S21=0.f,S22=0.f;
    float p00=0.f,p01=0.f,p02=0.f,p11=0.f,p12=0.f,p22=0.f;
    float q0=0.f,q1=0.f,q2=0.f;

    for (int k = 0; k < cnt; k++) {
        int   j = nbrList[start + k];
        float w = wMat[start + k];
        EDGE_ACC(B, j, w)
    }

    solve_and_store(S00,S01,S02,S10,S11,S12,S20,S21,S22,
                    p00,p01,p02,p11,p12,p22,q0,q1,q2,
                    arapW, out, b, i, N, total);
}

extern "C" void kernel_launch(void* const* d_in, const int* in_sizes, int n_in,
                              void* d_out, int out_size) {
    const float* xyz1 = (const float*)d_in[0];
    const float* xyz2 = (const float*)d_in[1];
    const int*   nbr  = (const int*)d_in[2];
    const int*   numN = (const int*)d_in[3];
    const int*   accN = (const int*)d_in[4];
    const float* wM   = (const float*)d_in[5];
    const float* aw   = (const float*)d_in[6];

    int N = in_sizes[3];                 // numNeighbors has N entries
    int B = in_sizes[0] / (3 * N);       // xyz1 is B*N*3
    int E = in_sizes[2];                 // neighborList length
    int total = B * N;

    int threads = 256;
    int blocks = (total + threads - 1) / threads;

    bool fast = (B == 4) && ((N & 127) == 0) && (E == 16 * N);

    if (fast) {
        pack4_smem<<<N / 128, 512>>>(xyz1, xyz2, N);
        arap_main4<<<blocks, threads>>>(nbr, wM, aw, (float*)d_out, N);
    } else {
        pack_naive<<<blocks, threads>>>(xyz1, xyz2, B, N);
        arap_main_gen<<<blocks, threads>>>(nbr, numN, accN, wM, aw,
                                           (float*)d_out, B, N);
    }
}

// round 9
// speedup vs baseline: 1.3727x; 1.1402x over previous
#include <cuda_runtime.h>

// ---------------------------------------------------------------------------
// ARAP forward — batch-interleaved gather layout, B=4 specialized.
// R9: branchless jrot (kills 9 BSSY/BSYNC pairs), 3 Jacobi sweeps,
//     edge-metadata preload (gather MLP), smem-staged coalesced outputs.
// NO register cap below 64 (proven twice that spill tax > occupancy gain);
// (256,4) pins the 64-reg point ptxas already picks.
// ---------------------------------------------------------------------------

#define MAXV (4 * 65536)

__device__ float4 g_pack2[2 * MAXV];   // index 2*(j*4+b) rest, +1 deformed

// B==4 pack: 128 vertices x 4 batches per 512-thread block, smem-staged.
__global__ void __launch_bounds__(512)
pack4_smem(const float* __restrict__ x1, const float* __restrict__ x2, int N) {
    __shared__ float s1[4 * 385];
    __shared__ float s2[4 * 385];
    int j0  = blockIdx.x * 128;
    int tid = threadIdx.x;

    for (int idx = tid; idx < 1536; idx += 512) {
        int b = idx / 384, k = idx - b * 384;
        s1[b * 385 + k] = x1[((size_t)b * N + j0) * 3 + k];
        s2[b * 385 + k] = x2[((size_t)b * N + j0) * 3 + k];
    }
    __syncthreads();

    int v = tid >> 2, b = tid & 3;
    int j = j0 + v;
    int si = b * 385 + v * 3;
    int t = j * 4 + b;
    g_pack2[2 * t]     = make_float4(s1[si], s1[si + 1], s1[si + 2], 0.f);
    g_pack2[2 * t + 1] = make_float4(s2[si], s2[si + 1], s2[si + 2], 0.f);
}

// Generic fallback pack (any B).
__global__ void pack_naive(const float* __restrict__ x1,
                           const float* __restrict__ x2,
                           int B, int N) {
    int t = blockIdx.x * blockDim.x + threadIdx.x;
    if (t >= B * N) return;
    int i = t / B, b = t - i * B;
    const float* p1 = x1 + ((size_t)b * N + i) * 3;
    const float* p2 = x2 + ((size_t)b * N + i) * 3;
    g_pack2[2 * t]     = make_float4(p1[0], p1[1], p1[2], 0.f);
    g_pack2[2 * t + 1] = make_float4(p2[0], p2[1], p2[2], 0.f);
}

// Branchless fast Jacobi rotation. Only pathological case is apq ~ 0 AND
// aqq ~ app (0/0 -> NaN); selects force the identity rotation there.
__device__ __forceinline__ void jrot(float A[3][3], float V[3][3], int p, int q) {
    float apq = A[p][q];
    bool ok = fabsf(apq) > 1e-20f;
    float app = A[p][p], aqq = A[q][q];
    float tau = __fdividef(aqq - app, 2.0f * apq);
    float tt  = __fdividef(copysignf(1.0f, tau),
                           fabsf(tau) + sqrtf(1.0f + tau * tau));
    tt = ok ? tt : 0.f;
    float c = rsqrtf(1.0f + tt * tt);
    float s = tt * c;
    int r = 3 - p - q;
    float arp = A[r][p], arq = A[r][q];
    A[p][p] = app - tt * apq;
    A[q][q] = aqq + tt * apq;
    A[p][q] = 0.f; A[q][p] = 0.f;
    float nrp = c * arp - s * arq;
    float nrq = s * arp + c * arq;
    A[r][p] = nrp; A[p][r] = nrp;
    A[r][q] = nrq; A[q][r] = nrq;
    #pragma unroll
    for (int i = 0; i < 3; i++) {
        float vip = V[i][p], viq = V[i][q];
        V[i][p] = c * vip - s * viq;
        V[i][q] = s * vip + c * viq;
    }
}

__device__ __forceinline__ void swap_col(float V[3][3], int a, int b) {
    #pragma unroll
    for (int i = 0; i < 3; i++) {
        float tmp = V[i][a]; V[i][a] = V[i][b]; V[i][b] = tmp;
    }
}

// Computes R (row-major in R[9]) and energies e[3] from the moments.
__device__ __forceinline__ void solve_cell(
    float S00, float S01, float S02, float S10, float S11, float S12,
    float S20, float S21, float S22,
    float p00, float p01, float p02, float p11, float p12, float p22,
    float q0, float q1, float q2,
    float* __restrict__ Rr, float* __restrict__ e)
{
    float S[3][3] = {{S00,S01,S02},{S10,S11,S12},{S20,S21,S22}};
    float A[3][3];
    #pragma unroll
    for (int p = 0; p < 3; p++)
        #pragma unroll
        for (int q = 0; q < 3; q++)
            A[p][q] = S[0][p] * S[0][q] + S[1][p] * S[1][q] + S[2][p] * S[2][q];

    float V[3][3] = {{1.f,0.f,0.f},{0.f,1.f,0.f},{0.f,0.f,1.f}};
    #pragma unroll
    for (int sw = 0; sw < 3; sw++) {
        jrot(A, V, 0, 1);
        jrot(A, V, 0, 2);
        jrot(A, V, 1, 2);
    }

    if (A[0][0] < A[1][1]) { float tmp=A[0][0]; A[0][0]=A[1][1]; A[1][1]=tmp; swap_col(V,0,1); }
    if (A[0][0] < A[2][2]) { float tmp=A[0][0]; A[0][0]=A[2][2]; A[2][2]=tmp; swap_col(V,0,2); }
    if (A[1][1] < A[2][2]) { float tmp=A[1][1]; A[1][1]=A[2][2]; A[2][2]=tmp; swap_col(V,1,2); }

    float v0x=V[0][0], v0y=V[1][0], v0z=V[2][0];
    float v1x=V[0][1], v1y=V[1][1], v1z=V[2][1];
    float v2x=V[0][2], v2y=V[1][2], v2z=V[2][2];

    float u0x = S[0][0]*v0x + S[0][1]*v0y + S[0][2]*v0z;
    float u0y = S[1][0]*v0x + S[1][1]*v0y + S[1][2]*v0z;
    float u0z = S[2][0]*v0x + S[2][1]*v0y + S[2][2]*v0z;
    float u1x = S[0][0]*v1x + S[0][1]*v1y + S[0][2]*v1z;
    float u1y = S[1][0]*v1x + S[1][1]*v1y + S[1][2]*v1z;
    float u1z = S[2][0]*v1x + S[2][1]*v1y + S[2][2]*v1z;
    float u2x = S[0][0]*v2x + S[0][1]*v2y + S[0][2]*v2z;
    float u2y = S[1][0]*v2x + S[1][1]*v2y + S[1][2]*v2z;
    float u2z = S[2][0]*v2x + S[2][1]*v2y + S[2][2]*v2z;

    float n0 = rsqrtf(fmaxf(u0x*u0x + u0y*u0y + u0z*u0z, 1e-30f));
    float n1 = rsqrtf(fmaxf(u1x*u1x + u1y*u1y + u1z*u1z, 1e-30f));
    float n2 = rsqrtf(fmaxf(u2x*u2x + u2y*u2y + u2z*u2z, 1e-30f));
    u0x*=n0; u0y*=n0; u0z*=n0;
    u1x*=n1; u1y*=n1; u1z*=n1;
    u2x*=n2; u2y*=n2; u2z*=n2;

    float detS = S[0][0]*(S[1][1]*S[2][2] - S[1][2]*S[2][1])
               - S[0][1]*(S[1][0]*S[2][2] - S[1][2]*S[2][0])
               + S[0][2]*(S[1][0]*S[2][1] - S[1][1]*S[2][0]);
    float sgn = (detS < 0.f) ? -1.f : 1.f;
    u2x *= sgn; u2y *= sgn; u2z *= sgn;

    float R00 = v0x*u0x + v1x*u1x + v2x*u2x;
    float R01 = v0x*u0y + v1x*u1y + v2x*u2y;
    float R02 = v0x*u0z + v1x*u1z + v2x*u2z;
    float R10 = v0y*u0x + v1y*u1x + v2y*u2x;
    float R11 = v0y*u0y + v1y*u1y + v2y*u2y;
    float R12 = v0y*u0z + v1y*u1z + v2y*u2z;
    float R20 = v0z*u0x + v1z*u1x + v2z*u2x;
    float R21 = v0z*u0y + v1z*u1y + v2z*u2y;
    float R22 = v0z*u0z + v1z*u1z + v2z*u2z;

    e[0] = fmaxf(q0
        - 2.f * (R00*S[0][0] + R01*S[1][0] + R02*S[2][0])
        + R00*R00*p00 + R01*R01*p11 + R02*R02*p22
        + 2.f * (R00*R01*p01 + R00*R02*p02 + R01*R02*p12), 0.f);
    e[1] = fmaxf(q1
        - 2.f * (R10*S[0][1] + R11*S[1][1] + R12*S[2][1])
        + R10*R10*p00 + R11*R11*p11 + R12*R12*p22
        + 2.f * (R10*R11*p01 + R10*R12*p02 + R11*R12*p12), 0.f);
    e[2] = fmaxf(q2
        - 2.f * (R20*S[0][2] + R21*S[1][2] + R22*S[2][2])
        + R20*R20*p00 + R21*R21*p11 + R22*R22*p22
        + 2.f * (R20*R21*p01 + R20*R22*p02 + R21*R22*p12), 0.f);

    Rr[0]=R00; Rr[1]=R01; Rr[2]=R02;
    Rr[3]=R10; Rr[4]=R11; Rr[5]=R12;
    Rr[6]=R20; Rr[7]=R21; Rr[8]=R22;
}

#define EDGE_ACC(Bv, j_, w_)                                                 \
    {                                                                        \
        const float4* pp = &g_pack2[2 * ((j_) * (Bv) + b)];                  \
        float4 p1v = pp[0], p2v = pp[1];                                     \
        float d1x = c1.x - p1v.x, d1y = c1.y - p1v.y, d1z = c1.z - p1v.z;    \
        float d2x = c2.x - p2v.x, d2y = c2.y - p2v.y, d2z = c2.z - p2v.z;    \
        float wx = (w_) * d1x, wy = (w_) * d1y, wz = (w_) * d1z;             \
        S00 += wx * d2x; S01 += wx * d2y; S02 += wx * d2z;                   \
        S10 += wy * d2x; S11 += wy * d2y; S12 += wy * d2z;                   \
        S20 += wz * d2x; S21 += wz * d2y; S22 += wz * d2z;                   \
        p00 += wx * d1x; p01 += wx * d1y; p02 += wx * d1z;                   \
        p11 += wy * d1y; p12 += wy * d1z; p22 += wz * d1z;                   \
        float vx = (w_) * d2x, vy = (w_) * d2y, vz = (w_) * d2z;             \
        q0 += vx * d2x; q1 += vy * d2y; q2 += vz * d2z;                      \
    }

// Specialized B==4, K==16, N%64==0 main kernel (grid is exact; no tail).
__global__ void __launch_bounds__(256, 4)
arap_main4(const int*   __restrict__ nbrList,
           const float* __restrict__ wMat,
           const float* __restrict__ arapW,
           float*       __restrict__ out,
           int N)
{
    // smem output staging (padded segment strides to dodge bank conflicts)
    __shared__ float se[4 * 196];   // energies: 64 v * 3 per batch
    __shared__ float sr[4 * 580];   // rotations: 64 v * 9 per batch

    int tid = threadIdx.x;
    int i0  = blockIdx.x * 64;
    int v   = tid >> 2;
    int b   = tid & 3;
    int i   = i0 + v;
    int t   = (i << 2) | b;
    int total = 4 * N;

    float4 c1 = g_pack2[2 * t];
    float4 c2 = g_pack2[2 * t + 1];
    int start = i << 4;             // accN[i] = 16*i (host-side guard)

    // Preload all edge metadata (8 independent LDG.128) before gathers.
    const int4*   nb4 = (const int4*)(nbrList + start);
    const float4* wv4 = (const float4*)(wMat + start);
    int4   nb0 = nb4[0], nb1 = nb4[1], nb2 = nb4[2], nb3 = nb4[3];
    float4 wv0 = wv4[0], wv1 = wv4[1], wv2 = wv4[2], wv3 = wv4[3];

    float S00=0.f,S01=0.f,S02=0.f,S10=0.f,S11=0.f,S12=0.f,S20=0.f,S21=0.f,S22=0.f;
    float p00=0.f,p01=0.f,p02=0.f,p11=0.f,p12=0.f,p22=0.f;
    float q0=0.f,q1=0.f,q2=0.f;

    EDGE_ACC(4, nb0.x, wv0.x) EDGE_ACC(4, nb0.y, wv0.y)
    EDGE_ACC(4, nb0.z, wv0.z) EDGE_ACC(4, nb0.w, wv0.w)
    EDGE_ACC(4, nb1.x, wv1.x) EDGE_ACC(4, nb1.y, wv1.y)
    EDGE_ACC(4, nb1.z, wv1.z) EDGE_ACC(4, nb1.w, wv1.w)
    EDGE_ACC(4, nb2.x, wv2.x) EDGE_ACC(4, nb2.y, wv2.y)
    EDGE_ACC(4, nb2.z, wv2.z) EDGE_ACC(4, nb2.w, wv2.w)
    EDGE_ACC(4, nb3.x, wv3.x) EDGE_ACC(4, nb3.y, wv3.y)
    EDGE_ACC(4, nb3.z, wv3.z) EDGE_ACC(4, nb3.w, wv3.w)

    float Rr[9], e[3];
    solve_cell(S00,S01,S02,S10,S11,S12,S20,S21,S22,
               p00,p01,p02,p11,p12,p22,q0,q1,q2, Rr, e);

    float aw = arapW[0];
    se[b * 196 + v * 3 + 0] = aw * e[0];
    se[b * 196 + v * 3 + 1] = aw * e[1];
    se[b * 196 + v * 3 + 2] = aw * e[2];
    #pragma unroll
    for (int k = 0; k < 9; k++) sr[b * 580 + v * 9 + k] = Rr[k];

    __syncthreads();

    // Energies: 4 segments x 48 float4, fully coalesced.
    if (tid < 192) {
        int bb = tid / 48, k = tid - bb * 48;
        float4* dst = (float4*)(out + ((size_t)bb * N + i0) * 3);
        dst[k] = ((const float4*)(se + bb * 196))[k];
    }
    // Rotations: 4 segments x 144 float4.
    #pragma unroll
    for (int idx = tid; idx < 576; idx += 256) {
        int bb = idx / 144, k = idx - bb * 144;
        float4* dst = (float4*)(out + (size_t)total * 3 + ((size_t)bb * N + i0) * 9);
        dst[k] = ((const float4*)(sr + bb * 580))[k];
    }
}

// Generic fallback (any B / ragged CSR), direct stores.
__global__ void __launch_bounds__(256)
arap_main_gen(const int*   __restrict__ nbrList,
              const int*   __restrict__ numN,
              const int*   __restrict__ accN,
              const float* __restrict__ wMat,
              const float* __restrict__ arapW,
              float*       __restrict__ out,
              int B, int N)
{
    int t = blockIdx.x * blockDim.x + threadIdx.x;
    int total = B * N;
    if (t >= total) return;
    int i = t / B;
    int b = t - i * B;

    float4 c1 = g_pack2[2 * t];
    float4 c2 = g_pack2[2 * t + 1];
    int start = accN[i];
    int cnt   = numN[i];

    float S00=0.f,S01=0.f,S02=0.f,S10=0.f,S11=0.f,S12=0.f,S20=0.f,S21=0.f,S22=0.f;
    float p00=0.f,p01=0.f,p02=0.f,p11=0.f,p12=0.f,p22=0.f;
    float q0=0.f,q1=0.f,q2=0.f;

    for (int k = 0; k < cnt; k++) {
        int   j = nbrList[start + k];
        float w = wMat[start + k];
        EDGE_ACC(B, j, w)
    }

    float Rr[9], e[3];
    solve_cell(S00,S01,S02,S10,S11,S12,S20,S21,S22,
               p00,p01,p02,p11,p12,p22,q0,q1,q2, Rr, e);

    float aw = arapW[0];
    int told = b * N + i;
    size_t eo = (size_t)told * 3;
    out[eo + 0] = aw * e[0];
    out[eo + 1] = aw * e[1];
    out[eo + 2] = aw * e[2];
    size_t ro = (size_t)total * 3 + (size_t)told * 9;
    #pragma unroll
    for (int k = 0; k < 9; k++) out[ro + k] = Rr[k];
}

extern "C" void kernel_launch(void* const* d_in, const int* in_sizes, int n_in,
                              void* d_out, int out_size) {
    const float* xyz1 = (const float*)d_in[0];
    const float* xyz2 = (const float*)d_in[1];
    const int*   nbr  = (const int*)d_in[2];
    const int*   numN = (const int*)d_in[3];
    const int*   accN = (const int*)d_in[4];
    const float* wM   = (const float*)d_in[5];
    const float* aw   = (const float*)d_in[6];

    int N = in_sizes[3];                 // numNeighbors has N entries
    int B = in_sizes[0] / (3 * N);       // xyz1 is B*N*3
    int E = in_sizes[2];                 // neighborList length
    int total = B * N;

    int threads = 256;
    int blocks = (total + threads - 1) / threads;

    bool fast = (B == 4) && ((N & 127) == 0) && (E == 16 * N);

    if (fast) {
        pack4_smem<<<N / 128, 512>>>(xyz1, xyz2, N);
        arap_main4<<<total / 256, threads>>>(nbr, wM, aw, (float*)d_out, N);
    } else {
        pack_naive<<<blocks, threads>>>(xyz1, xyz2, B, N);
        arap_main_gen<<<blocks, threads>>>(nbr, numN, accN, wM, aw,
                                           (float*)d_out, B, N);
    }
}

// round 10
// speedup vs baseline: 1.4987x; 1.0918x over previous
#include <cuda_runtime.h>

// ---------------------------------------------------------------------------
// ARAP forward — batch-interleaved gather layout, B=4 specialized.
// R10: closed-form symmetric 3x3 eigensolver (trig eigenvalues + cross-product
//      eigenvectors) replaces 9-rotation Jacobi + sort: ~240 fewer instr/thread
//      on a ~50% issue-bound kernel.
// Kept: 64-reg point (no cap below), metadata preload, smem-staged coalesced
// outputs, single-pass algebraic energies.
// ---------------------------------------------------------------------------

#define MAXV (4 * 65536)

__device__ float4 g_pack2[2 * MAXV];   // index 2*(j*4+b) rest, +1 deformed

// B==4 pack: 128 vertices x 4 batches per 512-thread block, smem-staged.
__global__ void __launch_bounds__(512)
pack4_smem(const float* __restrict__ x1, const float* __restrict__ x2, int N) {
    __shared__ float s1[4 * 385];
    __shared__ float s2[4 * 385];
    int j0  = blockIdx.x * 128;
    int tid = threadIdx.x;

    for (int idx = tid; idx < 1536; idx += 512) {
        int b = idx / 384, k = idx - b * 384;
        s1[b * 385 + k] = x1[((size_t)b * N + j0) * 3 + k];
        s2[b * 385 + k] = x2[((size_t)b * N + j0) * 3 + k];
    }
    __syncthreads();

    int v = tid >> 2, b = tid & 3;
    int j = j0 + v;
    int si = b * 385 + v * 3;
    int t = j * 4 + b;
    g_pack2[2 * t]     = make_float4(s1[si], s1[si + 1], s1[si + 2], 0.f);
    g_pack2[2 * t + 1] = make_float4(s2[si], s2[si + 1], s2[si + 2], 0.f);
}

// Generic fallback pack (any B).
__global__ void pack_naive(const float* __restrict__ x1,
                           const float* __restrict__ x2,
                           int B, int N) {
    int t = blockIdx.x * blockDim.x + threadIdx.x;
    if (t >= B * N) return;
    int i = t / B, b = t - i * B;
    const float* p1 = x1 + ((size_t)b * N + i) * 3;
    const float* p2 = x2 + ((size_t)b * N + i) * 3;
    g_pack2[2 * t]     = make_float4(p1[0], p1[1], p1[2], 0.f);
    g_pack2[2 * t + 1] = make_float4(p2[0], p2[1], p2[2], 0.f);
}

__device__ __forceinline__ float3 cross3(float ax, float ay, float az,
                                         float bx, float by, float bz) {
    return make_float3(ay * bz - az * by,
                       az * bx - ax * bz,
                       ax * by - ay * bx);
}

// Unit eigenvector of symmetric A for eigenvalue lam: max-norm cross product
// of rows of (A - lam I). Select-based, no branches.
__device__ __forceinline__ float3 eigvec(const float A[3][3], float lam) {
    float r0x = A[0][0] - lam, r0y = A[0][1],       r0z = A[0][2];
    float r1x = A[1][0],       r1y = A[1][1] - lam, r1z = A[1][2];
    float r2x = A[2][0],       r2y = A[2][1],       r2z = A[2][2] - lam;
    float3 c0 = cross3(r0x, r0y, r0z, r1x, r1y, r1z);
    float3 c1 = cross3(r0x, r0y, r0z, r2x, r2y, r2z);
    float3 c2 = cross3(r1x, r1y, r1z, r2x, r2y, r2z);
    float n0 = c0.x*c0.x + c0.y*c0.y + c0.z*c0.z;
    float n1 = c1.x*c1.x + c1.y*c1.y + c1.z*c1.z;
    float n2 = c2.x*c2.x + c2.y*c2.y + c2.z*c2.z;

    float3 best = c0; float nb = n0;
    best = (n1 > nb) ? c1 : best; nb = (n1 > nb) ? n1 : nb;
    best = (n2 > nb) ? c2 : best; nb = (n2 > nb) ? n2 : nb;
    bool bad = nb < 1e-28f;
    best.x = bad ? 1.f : best.x;
    best.y = bad ? 0.f : best.y;
    best.z = bad ? 0.f : best.z;
    nb     = bad ? 1.f : nb;
    float inv = rsqrtf(nb);
    return make_float3(best.x * inv, best.y * inv, best.z * inv);
}

// Computes R (row-major in Rr[9]) and energies e[3] from the moments.
__device__ __forceinline__ void solve_cell(
    float S00, float S01, float S02, float S10, float S11, float S12,
    float S20, float S21, float S22,
    float p00, float p01, float p02, float p11, float p12, float p22,
    float q0, float q1, float q2,
    float* __restrict__ Rr, float* __restrict__ e)
{
    float S[3][3] = {{S00,S01,S02},{S10,S11,S12},{S20,S21,S22}};
    float A[3][3];
    #pragma unroll
    for (int p = 0; p < 3; p++)
        #pragma unroll
        for (int q = 0; q < 3; q++)
            A[p][q] = S[0][p] * S[0][q] + S[1][p] * S[1][q] + S[2][p] * S[2][q];

    // ---- closed-form eigenvalues of symmetric A (sorted lam0>=lam1>=lam2) --
    float m   = (A[0][0] + A[1][1] + A[2][2]) * (1.f / 3.f);
    float k00 = A[0][0] - m, k11 = A[1][1] - m, k22 = A[2][2] - m;
    float off = A[0][1]*A[0][1] + A[0][2]*A[0][2] + A[1][2]*A[1][2];
    float p2  = k00*k00 + k11*k11 + k22*k22 + 2.f * off;
    float p   = sqrtf(p2 * (1.f / 6.f));
    float pinv = __fdividef(1.f, fmaxf(p, 1e-20f));
    float b00 = k00 * pinv, b11 = k11 * pinv, b22 = k22 * pinv;
    float b01 = A[0][1] * pinv, b02 = A[0][2] * pinv, b12 = A[1][2] * pinv;
    float detB = b00 * (b11 * b22 - b12 * b12)
               - b01 * (b01 * b22 - b12 * b02)
               + b02 * (b01 * b12 - b11 * b02);
    float rr  = fminf(fmaxf(0.5f * detB, -1.f), 1.f);
    float phi = acosf(rr) * (1.f / 3.f);
    float lam0 = m + 2.f * p * __cosf(phi);
    float lam2 = m + 2.f * p * __cosf(phi + 2.0943951023931953f);

    // ---- eigenvectors: principal (lam0) and minor (lam2) -------------------
    float3 v0 = eigvec(A, lam0);
    float3 v2r = eigvec(A, lam2);
    // Gram-Schmidt v2 against v0
    float d02 = v2r.x*v0.x + v2r.y*v0.y + v2r.z*v0.z;
    float wx = v2r.x - d02*v0.x, wy = v2r.y - d02*v0.y, wz = v2r.z - d02*v0.z;
    float nw = wx*wx + wy*wy + wz*wz;
    // fallback if v2r was parallel to v0 (deep degeneracy)
    float3 alt = cross3(v0.x, v0.y, v0.z, 0.345f, 0.767f, 0.539f);
    float nalt = alt.x*alt.x + alt.y*alt.y + alt.z*alt.z;
    bool bad = nw < 1e-24f;
    wx = bad ? alt.x : wx; wy = bad ? alt.y : wy; wz = bad ? alt.z : wz;
    nw = bad ? nalt : nw;
    float invw = rsqrtf(fmaxf(nw, 1e-30f));
    float v2x = wx * invw, v2y = wy * invw, v2z = wz * invw;
    // v1 = v2 x v0 (unit; column sign is irrelevant, cancels in v u^T)
    float3 v1c = cross3(v2x, v2y, v2z, v0.x, v0.y, v0.z);

    float v0x = v0.x, v0y = v0.y, v0z = v0.z;
    float v1x = v1c.x, v1y = v1c.y, v1z = v1c.z;

    // ---- u_j = normalize(S v_j) --------------------------------------------
    float u0x = S[0][0]*v0x + S[0][1]*v0y + S[0][2]*v0z;
    float u0y = S[1][0]*v0x + S[1][1]*v0y + S[1][2]*v0z;
    float u0z = S[2][0]*v0x + S[2][1]*v0y + S[2][2]*v0z;
    float u1x = S[0][0]*v1x + S[0][1]*v1y + S[0][2]*v1z;
    float u1y = S[1][0]*v1x + S[1][1]*v1y + S[1][2]*v1z;
    float u1z = S[2][0]*v1x + S[2][1]*v1y + S[2][2]*v1z;
    float u2x = S[0][0]*v2x + S[0][1]*v2y + S[0][2]*v2z;
    float u2y = S[1][0]*v2x + S[1][1]*v2y + S[1][2]*v2z;
    float u2z = S[2][0]*v2x + S[2][1]*v2y + S[2][2]*v2z;

    float n0 = rsqrtf(fmaxf(u0x*u0x + u0y*u0y + u0z*u0z, 1e-30f));
    float n1 = rsqrtf(fmaxf(u1x*u1x + u1y*u1y + u1z*u1z, 1e-30f));
    float n2 = rsqrtf(fmaxf(u2x*u2x + u2y*u2y + u2z*u2z, 1e-30f));
    u0x*=n0; u0y*=n0; u0z*=n0;
    u1x*=n1; u1y*=n1; u1z*=n1;
    u2x*=n2; u2y*=n2; u2z*=n2;

    float detS = S[0][0]*(S[1][1]*S[2][2] - S[1][2]*S[2][1])
               - S[0][1]*(S[1][0]*S[2][2] - S[1][2]*S[2][0])
               + S[0][2]*(S[1][0]*S[2][1] - S[1][1]*S[2][0]);
    float sgn = (detS < 0.f) ? -1.f : 1.f;
    u2x *= sgn; u2y *= sgn; u2z *= sgn;

    float R00 = v0x*u0x + v1x*u1x + v2x*u2x;
    float R01 = v0x*u0y + v1x*u1y + v2x*u2y;
    float R02 = v0x*u0z + v1x*u1z + v2x*u2z;
    float R10 = v0y*u0x + v1y*u1x + v2y*u2x;
    float R11 = v0y*u0y + v1y*u1y + v2y*u2y;
    float R12 = v0y*u0z + v1y*u1z + v2y*u2z;
    float R20 = v0z*u0x + v1z*u1x + v2z*u2x;
    float R21 = v0z*u0y + v1z*u1y + v2z*u2y;
    float R22 = v0z*u0z + v1z*u1z + v2z*u2z;

    e[0] = fmaxf(q0
        - 2.f * (R00*S[0][0] + R01*S[1][0] + R02*S[2][0])
        + R00*R00*p00 + R01*R01*p11 + R02*R02*p22
        + 2.f * (R00*R01*p01 + R00*R02*p02 + R01*R02*p12), 0.f);
    e[1] = fmaxf(q1
        - 2.f * (R10*S[0][1] + R11*S[1][1] + R12*S[2][1])
        + R10*R10*p00 + R11*R11*p11 + R12*R12*p22
        + 2.f * (R10*R11*p01 + R10*R12*p02 + R11*R12*p12), 0.f);
    e[2] = fmaxf(q2
        - 2.f * (R20*S[0][2] + R21*S[1][2] + R22*S[2][2])
        + R20*R20*p00 + R21*R21*p11 + R22*R22*p22
        + 2.f * (R20*R21*p01 + R20*R22*p02 + R21*R22*p12), 0.f);

    Rr[0]=R00; Rr[1]=R01; Rr[2]=R02;
    Rr[3]=R10; Rr[4]=R11; Rr[5]=R12;
    Rr[6]=R20; Rr[7]=R21; Rr[8]=R22;
}

#define EDGE_ACC(Bv, j_, w_)                                                 \
    {                                                                        \
        const float4* pp = &g_pack2[2 * ((j_) * (Bv) + b)];                  \
        float4 p1v = pp[0], p2v = pp[1];                                     \
        float d1x = c1.x - p1v.x, d1y = c1.y - p1v.y, d1z = c1.z - p1v.z;    \
        float d2x = c2.x - p2v.x, d2y = c2.y - p2v.y, d2z = c2.z - p2v.z;    \
        float wx = (w_) * d1x, wy = (w_) * d1y, wz = (w_) * d1z;             \
        S00 += wx * d2x; S01 += wx * d2y; S02 += wx * d2z;                   \
        S10 += wy * d2x; S11 += wy * d2y; S12 += wy * d2z;                   \
        S20 += wz * d2x; S21 += wz * d2y; S22 += wz * d2z;                   \
        p00 += wx * d1x; p01 += wx * d1y; p02 += wx * d1z;                   \
        p11 += wy * d1y; p12 += wy * d1z; p22 += wz * d1z;                   \
        float vx = (w_) * d2x, vy = (w_) * d2y, vz = (w_) * d2z;             \
        q0 += vx * d2x; q1 += vy * d2y; q2 += vz * d2z;                      \
    }

// Specialized B==4, K==16, N%64==0 main kernel (grid is exact; no tail).
__global__ void __launch_bounds__(256, 4)
arap_main4(const int*   __restrict__ nbrList,
           const float* __restrict__ wMat,
           const float* __restrict__ arapW,
           float*       __restrict__ out,
           int N)
{
    __shared__ float se[4 * 196];   // energies: 64 v * 3 per batch
    __shared__ float sr[4 * 580];   // rotations: 64 v * 9 per batch

    int tid = threadIdx.x;
    int i0  = blockIdx.x * 64;
    int v   = tid >> 2;
    int b   = tid & 3;
    int i   = i0 + v;
    int t   = (i << 2) | b;
    int total = 4 * N;

    float4 c1 = g_pack2[2 * t];
    float4 c2 = g_pack2[2 * t + 1];
    int start = i << 4;             // accN[i] = 16*i (host-side guard)

    const int4*   nb4 = (const int4*)(nbrList + start);
    const float4* wv4 = (const float4*)(wMat + start);
    int4   nb0 = nb4[0], nb1 = nb4[1], nb2 = nb4[2], nb3 = nb4[3];
    float4 wv0 = wv4[0], wv1 = wv4[1], wv2 = wv4[2], wv3 = wv4[3];

    float S00=0.f,S01=0.f,S02=0.f,S10=0.f,S11=0.f,S12=0.f,S20=0.f,S21=0.f,S22=0.f;
    float p00=0.f,p01=0.f,p02=0.f,p11=0.f,p12=0.f,p22=0.f;
    float q0=0.f,q1=0.f,q2=0.f;

    EDGE_ACC(4, nb0.x, wv0.x) EDGE_ACC(4, nb0.y, wv0.y)
    EDGE_ACC(4, nb0.z, wv0.z) EDGE_ACC(4, nb0.w, wv0.w)
    EDGE_ACC(4, nb1.x, wv1.x) EDGE_ACC(4, nb1.y, wv1.y)
    EDGE_ACC(4, nb1.z, wv1.z) EDGE_ACC(4, nb1.w, wv1.w)
    EDGE_ACC(4, nb2.x, wv2.x) EDGE_ACC(4, nb2.y, wv2.y)
    EDGE_ACC(4, nb2.z, wv2.z) EDGE_ACC(4, nb2.w, wv2.w)
    EDGE_ACC(4, nb3.x, wv3.x) EDGE_ACC(4, nb3.y, wv3.y)
    EDGE_ACC(4, nb3.z, wv3.z) EDGE_ACC(4, nb3.w, wv3.w)

    float Rr[9], e[3];
    solve_cell(S00,S01,S02,S10,S11,S12,S20,S21,S22,
               p00,p01,p02,p11,p12,p22,q0,q1,q2, Rr, e);

    float aw = arapW[0];
    se[b * 196 + v * 3 + 0] = aw * e[0];
    se[b * 196 + v * 3 + 1] = aw * e[1];
    se[b * 196 + v * 3 + 2] = aw * e[2];
    #pragma unroll
    for (int k = 0; k < 9; k++) sr[b * 580 + v * 9 + k] = Rr[k];

    __syncthreads();

    if (tid < 192) {
        int bb = tid / 48, k = tid - bb * 48;
        float4* dst = (float4*)(out + ((size_t)bb * N + i0) * 3);
        dst[k] = ((const float4*)(se + bb * 196))[k];
    }
    #pragma unroll
    for (int idx = tid; idx < 576; idx += 256) {
        int bb = idx / 144, k = idx - bb * 144;
        float4* dst = (float4*)(out + (size_t)total * 3 + ((size_t)bb * N + i0) * 9);
        dst[k] = ((const float4*)(sr + bb * 580))[k];
    }
}

// Generic fallback (any B / ragged CSR), direct stores.
__global__ void __launch_bounds__(256)
arap_main_gen(const int*   __restrict__ nbrList,
              const int*   __restrict__ numN,
              const int*   __restrict__ accN,
              const float* __restrict__ wMat,
              const float* __restrict__ arapW,
              float*       __restrict__ out,
              int B, int N)
{
    int t = blockIdx.x * blockDim.x + threadIdx.x;
    int total = B * N;
    if (t >= total) return;
    int i = t / B;
    int b = t - i * B;

    float4 c1 = g_pack2[2 * t];
    float4 c2 = g_pack2[2 * t + 1];
    int start = accN[i];
    int cnt   = numN[i];

    float S00=0.f,S01=0.f,S02=0.f,S10=0.f,S11=0.f,S12=0.f,S20=0.f,S21=0.f,S22=0.f;
    float p00=0.f,p01=0.f,p02=0.f,p11=0.f,p12=0.f,p22=0.f;
    float q0=0.f,q1=0.f,q2=0.f;

    for (int k = 0; k < cnt; k++) {
        int   j = nbrList[start + k];
        float w = wMat[start + k];
        EDGE_ACC(B, j, w)
    }

    float Rr[9], e[3];
    solve_cell(S00,S01,S02,S10,S11,S12,S20,S21,S22,
               p00,p01,p02,p11,p12,p22,q0,q1,q2, Rr, e);

    float aw = arapW[0];
    int told = b * N + i;
    size_t eo = (size_t)told * 3;
    out[eo + 0] = aw * e[0];
    out[eo + 1] = aw * e[1];
    out[eo + 2] = aw * e[2];
    size_t ro = (size_t)total * 3 + (size_t)told * 9;
    #pragma unroll
    for (int k = 0; k < 9; k++) out[ro + k] = Rr[k];
}

extern "C" void kernel_launch(void* const* d_in, const int* in_sizes, int n_in,
                              void* d_out, int out_size) {
    const float* xyz1 = (const float*)d_in[0];
    const float* xyz2 = (const float*)d_in[1];
    const int*   nbr  = (const int*)d_in[2];
    const int*   numN = (const int*)d_in[3];
    const int*   accN = (const int*)d_in[4];
    const float* wM   = (const float*)d_in[5];
    const float* aw   = (const float*)d_in[6];

    int N = in_sizes[3];                 // numNeighbors has N entries
    int B = in_sizes[0] / (3 * N);       // xyz1 is B*N*3
    int E = in_sizes[2];                 // neighborList length
    int total = B * N;

    int threads = 256;
    int blocks = (total + threads - 1) / threads;

    bool fast = (B == 4) && ((N & 127) == 0) && (E == 16 * N);

    if (fast) {
        pack4_smem<<<N / 128, 512>>>(xyz1, xyz2, N);
        arap_main4<<<total / 256, threads>>>(nbr, wM, aw, (float*)d_out, N);
    } else {
        pack_naive<<<blocks, threads>>>(xyz1, xyz2, B, N);
        arap_main_gen<<<blocks, threads>>>(nbr, numN, accN, wM, aw,
                                           (float*)d_out, B, N);
    }
}